// round 1
// baseline (speedup 1.0000x reference)
#include <cuda_runtime.h>
#include <cuda_bf16.h>
#include <math.h>

// Problem constants
#define BWIN   4096     // number of windows (B_)
#define NTOK   49       // tokens per window (7x7)
#define CDIM   256      // channels
#define HEADS  8
#define HDIM   32
#define NWIN   64       // windows per image (B_/B_global)
#define SCALE  0.17677669529663688f   // 32^-0.5

// SMEM layout (in floats)
#define XS     264            // padded row stride for x/out tile (mult of 4)
#define KP     36             // padded row stride for k/v per-head tiles (mult of 4)
#define NROWPAD 56            // 49 padded to 8*7
#define SM_X_OFF   0
#define SM_W_OFF   (NROWPAD*XS)                 // 14784
#define SM_K_OFF   (SM_W_OFF + 16*512)          // 22976
#define SM_V_OFF   (SM_K_OFF + HEADS*NTOK*KP)   // 37088
#define SM_TOTAL_F (SM_V_OFF + HEADS*NTOK*KP)   // 51200 floats
#define SM_BYTES   (SM_TOTAL_F*4)               // 204800 B

// Scratch: pre-transposed weights + precomputed (transposed) relative bias
__device__ float g_wT_qkv[256*512];     // [kin][out]
__device__ float g_wT_proj[256*256];    // [kin][out]
__device__ float g_biasT[HEADS*NTOK*NTOK]; // [h][key][query]

__global__ void wag_prep(const float* __restrict__ qkv_w,
                         const float* __restrict__ proj_w,
                         const float* __restrict__ rbt)
{
    int t = blockIdx.x * 256 + threadIdx.x;   // grid covers 131072 = 512*256
    // qkv_w [512,256] -> g_wT_qkv [256][512]
    if (t < 512*256) {
        int o = t >> 8, kin = t & 255;
        g_wT_qkv[kin*512 + o] = qkv_w[t];
    }
    // proj_w [256,256] -> g_wT_proj [256][256]
    if (t < 256*256) {
        int o = t >> 8, kin = t & 255;
        g_wT_proj[kin*256 + o] = proj_w[t];
    }
    // bias: g_biasT[h][j(key)][i(query)] = rbt[rpi(i,j)*8 + h]
    if (t < HEADS*NTOK*NTOK) {
        int h = t / (NTOK*NTOK);
        int r = t % (NTOK*NTOK);
        int i = r / NTOK;     // query
        int j = r % NTOK;     // key
        int ai = i / 7, aj = i % 7;
        int bi = j / 7, bj = j % 7;
        int idx = (ai - bi + 6) * 13 + (aj - bj + 6);
        g_biasT[(h*NTOK + j)*NTOK + i] = rbt[idx*HEADS + h];
    }
}

__global__ __launch_bounds__(256, 1)
void wag_main(const float* __restrict__ x, const float* __restrict__ qg,
              const float* __restrict__ qkvb, const float* __restrict__ projb,
              float* __restrict__ out)
{
    extern __shared__ float sm[];
    float* s_x = sm + SM_X_OFF;   // [56][264]  x tile, later attention output tile
    float* s_w = sm + SM_W_OFF;   // [16][512]  weight chunk
    float* s_k = sm + SM_K_OFF;   // [8][49][36]
    float* s_v = sm + SM_V_OFF;   // [8][49][36]

    const int tid = threadIdx.x;
    const int tx = tid & 31;
    const int wy = tid >> 5;      // warp id 0..7
    const int b  = blockIdx.x;

    // ---- Load x tile [49][256] -> s_x (float4 coalesced) ----
    {
        const float4* xb = (const float4*)(x + (size_t)b * NTOK * CDIM);
        for (int i = tid; i < NTOK * 64; i += 256) {
            int n = i >> 6, c4 = i & 63;
            float4 v = __ldg(xb + n*64 + c4);
            *(float4*)(s_x + n*XS + c4*4) = v;
        }
    }

    // ---- Phase 1: kv[49][512] = x[49][256] @ WqkvT, staged in 16-row K chunks ----
    float acc[7][16];
    #pragma unroll
    for (int i = 0; i < 7; i++)
        #pragma unroll
        for (int j = 0; j < 16; j++) acc[i][j] = 0.f;

    for (int k0 = 0; k0 < 256; k0 += 16) {
        __syncthreads();   // also orders the x-tile stores on first iteration
        const float4* wsrc = (const float4*)(g_wT_qkv + k0*512);
        for (int i = tid; i < 16*128; i += 256)
            *(float4*)(s_w + i*4) = __ldg(wsrc + i);
        __syncthreads();
        #pragma unroll
        for (int kk = 0; kk < 16; kk++) {
            float xv[7];
            #pragma unroll
            for (int i = 0; i < 7; i++) xv[i] = s_x[(wy*7 + i)*XS + k0 + kk];
            #pragma unroll
            for (int j = 0; j < 16; j++) {
                float wv = s_w[kk*512 + tx + 32*j];
                #pragma unroll
                for (int i = 0; i < 7; i++) acc[i][j] = fmaf(xv[i], wv, acc[i][j]);
            }
        }
    }

    // scatter k/v (+bias) into per-head padded SMEM tiles
    #pragma unroll
    for (int j = 0; j < 16; j++) {
        int c = tx + 32*j;                    // 0..511
        float bia = __ldg(qkvb + c);
        int h = (c >> 5) & 7;
        int d = c & 31;
        float* dst = ((c >= 256) ? s_v : s_k) + h*NTOK*KP + d;
        #pragma unroll
        for (int i = 0; i < 7; i++) {
            int r = wy*7 + i;
            if (r < NTOK) dst[r*KP] = acc[i][j] + bia;
        }
    }
    __syncthreads();

    // ---- Phase 2: per-head attention; warp wy handles head wy ----
    {
        const int h = wy;
        const float* qbase = qg + ((size_t)(b >> 6) * HEADS + h) * NTOK * HDIM;
        const float* kh = s_k + h*NTOK*KP;
        const float* vh = s_v + h*NTOK*KP;

        #pragma unroll
        for (int p = 0; p < 2; p++) {
            int qi = p*32 + tx;
            bool act = qi < NTOK;
            int qis = act ? qi : 0;

            float qv[32];
            {
                const float4* qr = (const float4*)(qbase + qis*HDIM);
                #pragma unroll
                for (int d4 = 0; d4 < 8; d4++) {
                    float4 t = __ldg(qr + d4);
                    float m = act ? SCALE : 0.f;
                    qv[d4*4+0] = t.x*m; qv[d4*4+1] = t.y*m;
                    qv[d4*4+2] = t.z*m; qv[d4*4+3] = t.w*m;
                }
            }

            float s[NTOK];
            #pragma unroll
            for (int kj = 0; kj < NTOK; kj++) {
                const float4* kr = (const float4*)(kh + kj*KP);  // broadcast across warp
                float sum = 0.f;
                #pragma unroll
                for (int d4 = 0; d4 < 8; d4++) {
                    float4 kv4 = kr[d4];
                    sum = fmaf(qv[d4*4+0], kv4.x, sum);
                    sum = fmaf(qv[d4*4+1], kv4.y, sum);
                    sum = fmaf(qv[d4*4+2], kv4.z, sum);
                    sum = fmaf(qv[d4*4+3], kv4.w, sum);
                }
                s[kj] = sum;
            }

            // + bias, softmax (bias transposed: coalesced over query lanes)
            float mx = -1e30f;
            #pragma unroll
            for (int kj = 0; kj < NTOK; kj++) {
                float bv = __ldg(g_biasT + (h*NTOK + kj)*NTOK + qis);
                s[kj] += bv;
                mx = fmaxf(mx, s[kj]);
            }
            float sum = 0.f;
            #pragma unroll
            for (int kj = 0; kj < NTOK; kj++) {
                s[kj] = __expf(s[kj] - mx);
                sum += s[kj];
            }
            float rinv = 1.f / sum;

            float o[32];
            #pragma unroll
            for (int d = 0; d < 32; d++) o[d] = 0.f;
            #pragma unroll
            for (int kj = 0; kj < NTOK; kj++) {
                float pv = s[kj];
                const float4* vr = (const float4*)(vh + kj*KP);  // broadcast
                #pragma unroll
                for (int d4 = 0; d4 < 8; d4++) {
                    float4 vv = vr[d4];
                    o[d4*4+0] = fmaf(pv, vv.x, o[d4*4+0]);
                    o[d4*4+1] = fmaf(pv, vv.y, o[d4*4+1]);
                    o[d4*4+2] = fmaf(pv, vv.z, o[d4*4+2]);
                    o[d4*4+3] = fmaf(pv, vv.w, o[d4*4+3]);
                }
            }
            if (act) {
                float4* dst = (float4*)(s_x + qi*XS + h*HDIM);
                #pragma unroll
                for (int d4 = 0; d4 < 8; d4++)
                    dst[d4] = make_float4(o[d4*4+0]*rinv, o[d4*4+1]*rinv,
                                          o[d4*4+2]*rinv, o[d4*4+3]*rinv);
            }
        }
    }

    // ---- Phase 3: proj: out[49][256] = attn_out[49][256] @ WprojT + b ----
    float a2[7][8];
    #pragma unroll
    for (int i = 0; i < 7; i++)
        #pragma unroll
        for (int j = 0; j < 8; j++) a2[i][j] = 0.f;

    for (int k0 = 0; k0 < 256; k0 += 16) {
        __syncthreads();   // orders phase-2 s_x writes on first iteration
        const float4* wsrc = (const float4*)(g_wT_proj + k0*256);
        for (int i = tid; i < 16*64; i += 256)
            *(float4*)(s_w + i*4) = __ldg(wsrc + i);
        __syncthreads();
        #pragma unroll
        for (int kk = 0; kk < 16; kk++) {
            float xv[7];
            #pragma unroll
            for (int i = 0; i < 7; i++) xv[i] = s_x[(wy*7 + i)*XS + k0 + kk];
            #pragma unroll
            for (int j = 0; j < 8; j++) {
                float wv = s_w[kk*256 + tx + 32*j];
                #pragma unroll
                for (int i = 0; i < 7; i++) a2[i][j] = fmaf(xv[i], wv, a2[i][j]);
            }
        }
    }

    float* ob = out + (size_t)b * NTOK * CDIM;
    #pragma unroll
    for (int j = 0; j < 8; j++) {
        int c = tx + 32*j;
        float pb = __ldg(projb + c);
        #pragma unroll
        for (int i = 0; i < 7; i++) {
            int r = wy*7 + i;
            if (r < NTOK) ob[r*CDIM + c] = a2[i][j] + pb;   // coalesced per (i,j)
        }
    }
}

extern "C" void kernel_launch(void* const* d_in, const int* in_sizes, int n_in,
                              void* d_out, int out_size)
{
    const float* x      = (const float*)d_in[0];
    const float* qg     = (const float*)d_in[1];
    const float* qkv_w  = (const float*)d_in[2];
    const float* qkv_b  = (const float*)d_in[3];
    const float* proj_w = (const float*)d_in[4];
    const float* proj_b = (const float*)d_in[5];
    const float* rbt    = (const float*)d_in[6];
    float* out = (float*)d_out;

    (void)in_sizes; (void)n_in; (void)out_size;

    // Idempotent, capture-safe (not a stream op, no allocation)
    cudaFuncSetAttribute(wag_main, cudaFuncAttributeMaxDynamicSharedMemorySize, SM_BYTES);

    wag_prep<<<512, 256>>>(qkv_w, proj_w, rbt);
    wag_main<<<BWIN, 256, SM_BYTES>>>(x, qg, qkv_b, proj_b, out);
}

// round 3
// speedup vs baseline: 2.4013x; 2.4013x over previous
#include <cuda_runtime.h>
#include <cuda_bf16.h>
#include <cstdint>
#include <math.h>

#define NTOK   49
#define CDIM   256
#define HEADS  8
#define HDIM   32
#define BWIN   4096
#define TOKS   (BWIN*NTOK)          // 200704 = 1568 * 128
#define KD     768                  // hi | lo | hi split K
#define SCALE  0.17677669529663688f

// ---------------- scratch (device globals; no allocs) ----------------
__device__ __nv_bfloat16 g_A1[(size_t)TOKS*KD];   // x split   [t][768]
__device__ __nv_bfloat16 g_A2[(size_t)TOKS*KD];   // attn-out split
__device__ float         g_KV[(size_t)TOKS*512];  // k(0:256) v(256:512) fp32
__device__ __nv_bfloat16 g_B1[512*KD];            // qkv_w split  [n][768]
__device__ __nv_bfloat16 g_B2[256*KD];            // proj_w split
__device__ float         g_biasT[HEADS*NTOK*NTOK];// [h][key][query]

// ---------------- helpers ----------------
__device__ __forceinline__ uint32_t smem_u32(const void* p){
    uint32_t a;
    asm("{ .reg .u64 t; cvta.to.shared.u64 t, %1; cvt.u32.u64 %0, t; }" : "=r"(a) : "l"(p));
    return a;
}
__device__ __forceinline__ void cp_async16(uint32_t dst, const void* src){
    asm volatile("cp.async.cg.shared.global [%0], [%1], 16;" :: "r"(dst), "l"(src));
}
#define CP_COMMIT() asm volatile("cp.async.commit_group;")
#define CP_WAIT1()  asm volatile("cp.async.wait_group 1;")
#define CP_WAIT0()  asm volatile("cp.async.wait_group 0;")

__device__ __forceinline__ void ldmx4(uint32_t* r, uint32_t addr){
    asm volatile("ldmatrix.sync.aligned.m8n8.x4.shared.b16 {%0,%1,%2,%3}, [%4];"
        : "=r"(r[0]), "=r"(r[1]), "=r"(r[2]), "=r"(r[3]) : "r"(addr));
}
__device__ __forceinline__ void mma16816(float* c, const uint32_t* a, const uint32_t* b){
    asm volatile("mma.sync.aligned.m16n8k16.row.col.f32.bf16.bf16.f32 "
        "{%0,%1,%2,%3}, {%4,%5,%6,%7}, {%8,%9}, {%0,%1,%2,%3};"
        : "+f"(c[0]), "+f"(c[1]), "+f"(c[2]), "+f"(c[3])
        : "r"(a[0]), "r"(a[1]), "r"(a[2]), "r"(a[3]), "r"(b[0]), "r"(b[1]));
}

// ---------------- prep: weights -> split bf16, bias transpose ----------------
__global__ void prep_w(const float* __restrict__ qkv_w,
                       const float* __restrict__ proj_w,
                       const float* __restrict__ rbt)
{
    int idx = blockIdx.x * 256 + threadIdx.x;   // 1536*256 = 393216 = 512*768
    if (idx < 512*768) {
        int j = idx / 768, c = idx % 768;
        int cc = c & 255, sect = c >> 8;
        float wv = qkv_w[j*256 + cc];
        __nv_bfloat16 hi = __float2bfloat16(wv);
        g_B1[idx] = (sect < 2) ? hi : __float2bfloat16(wv - __bfloat162float(hi));
    }
    if (idx < 256*768) {
        int j = idx / 768, c = idx % 768;
        int cc = c & 255, sect = c >> 8;
        float wv = proj_w[j*256 + cc];
        __nv_bfloat16 hi = __float2bfloat16(wv);
        g_B2[idx] = (sect < 2) ? hi : __float2bfloat16(wv - __bfloat162float(hi));
    }
    if (idx < HEADS*NTOK*NTOK) {
        int h = idx / (NTOK*NTOK);
        int r = idx % (NTOK*NTOK);
        int i = r / NTOK, j = r % NTOK;     // i=query, j=key
        int ai = i / 7, aj = i % 7, bi = j / 7, bj = j % 7;
        int t = (ai - bi + 6) * 13 + (aj - bj + 6);
        g_biasT[(h*NTOK + j)*NTOK + i] = rbt[t*HEADS + h];
    }
}

// ---------------- convert x -> A1' (hi|lo|hi) ----------------
__global__ void conv_x(const float* __restrict__ x)
{
    size_t t = blockIdx.x;
    int c = threadIdx.x;
    float v = x[t*CDIM + c];
    __nv_bfloat16 hi = __float2bfloat16(v);
    __nv_bfloat16 lo = __float2bfloat16(v - __bfloat162float(hi));
    size_t rb = t * KD;
    g_A1[rb + c]       = hi;
    g_A1[rb + 256 + c] = lo;
    g_A1[rb + 512 + c] = hi;
}

// ---------------- mma.sync bf16 GEMM: C[128,128] per CTA, K=768 ----------------
// SMEM tile: [128 rows][64 bf16] = 128B rows, XOR-swizzled 16B chunks, x2 stages.
#define GSTAGE 16384     // bytes per (A or B) stage: 128*64*2
#define GSMEM  (4*GSTAGE)

template<int NOUT>
__global__ void __launch_bounds__(256)
gemm_k(const float* __restrict__ bias, float* __restrict__ extC)
{
    extern __shared__ char sm[];
    const __nv_bfloat16* Ag = (NOUT == 512) ? g_A1 : g_A2;
    const __nv_bfloat16* Bg = (NOUT == 512) ? g_B1 : g_B2;
    float* C = (NOUT == 512) ? g_KV : extC;

    const int tid = threadIdx.x;
    const int m0 = blockIdx.x * 128;
    const int n0 = blockIdx.y * 128;
    const uint32_t sb = smem_u32(sm);
    // stage s: A at sb + s*GSTAGE, B at sb + 2*GSTAGE + s*GSTAGE

    // -- async loader: 2048 16B chunks per stage (A:1024, B:1024), 8 per thread --
    auto load_stage = [&](int i, int s){
        const char* Abase = (const char*)Ag + ((size_t)m0*KD + (size_t)i*64)*2;
        const char* Bbase = (const char*)Bg + ((size_t)n0*KD + (size_t)i*64)*2;
        uint32_t sa = sb + s*GSTAGE;
        uint32_t sbB = sb + 2*GSTAGE + s*GSTAGE;
        #pragma unroll
        for (int u = 0; u < 4; u++) {
            int idx = tid + u*256;          // 0..1023
            int r = idx >> 3, c16 = idx & 7;
            uint32_t dst = (uint32_t)(r*128 + ((c16 ^ (r & 7))*16));
            cp_async16(sa  + dst, Abase + (size_t)r*(KD*2) + c16*16);
            cp_async16(sbB + dst, Bbase + (size_t)r*(KD*2) + c16*16);
        }
        CP_COMMIT();
    };

    const int w = tid >> 5, lane = tid & 31;
    const int wm = w >> 1, wn = w & 1;       // 4 x 2 warp grid
    // ldmatrix address components
    const int aRow = wm*32 + (lane & 15);               // + mt*16
    const int aC16 = (lane >> 4);                       // + kk*2
    const int bRow = wn*64 + (lane & 7) + ((lane >> 4) << 3);  // + np*16
    const int bC16 = (lane >> 3) & 1;                   // + kk*2

    float acc[2][8][4];
    #pragma unroll
    for (int mt = 0; mt < 2; mt++)
        #pragma unroll
        for (int nt = 0; nt < 8; nt++)
            #pragma unroll
            for (int q = 0; q < 4; q++) acc[mt][nt][q] = 0.f;

    load_stage(0, 0);
    for (int i = 0; i < 12; i++) {
        const int s = i & 1;
        if (i < 11) { load_stage(i+1, s^1); CP_WAIT1(); }
        else        { CP_WAIT0(); }
        __syncthreads();
        const uint32_t sa  = sb + s*GSTAGE;
        const uint32_t sbB = sb + 2*GSTAGE + s*GSTAGE;
        #pragma unroll
        for (int kk = 0; kk < 4; kk++) {
            uint32_t af[2][4];
            #pragma unroll
            for (int mt = 0; mt < 2; mt++) {
                int r = aRow + mt*16, c = kk*2 + aC16;
                ldmx4(af[mt], sa + r*128 + ((c ^ (r & 7))*16));
            }
            #pragma unroll
            for (int np = 0; np < 4; np++) {
                uint32_t bf[4];
                int r = bRow + np*16, c = kk*2 + bC16;
                ldmx4(bf, sbB + r*128 + ((c ^ (r & 7))*16));
                #pragma unroll
                for (int mt = 0; mt < 2; mt++) {
                    mma16816(acc[mt][np*2+0], af[mt], bf+0);
                    mma16816(acc[mt][np*2+1], af[mt], bf+2);
                }
            }
        }
        __syncthreads();
    }

    // -- epilogue: add bias, store fp32 --
    #pragma unroll
    for (int nt = 0; nt < 8; nt++) {
        int col = n0 + wn*64 + nt*8 + (lane & 3)*2;
        float bx = __ldg(bias + col), by = __ldg(bias + col + 1);
        #pragma unroll
        for (int mt = 0; mt < 2; mt++) {
            int row = m0 + wm*32 + mt*16 + (lane >> 2);
            float2 v0 = make_float2(acc[mt][nt][0] + bx, acc[mt][nt][1] + by);
            float2 v1 = make_float2(acc[mt][nt][2] + bx, acc[mt][nt][3] + by);
            *(float2*)(C + (size_t)row*NOUT + col)       = v0;
            *(float2*)(C + (size_t)(row+8)*NOUT + col)   = v1;
        }
    }
}

// ---------------- attention (fp32 SIMT), writes A2' split ----------------
#define ATTN_SMEM ((49*512 + 49*264) * 4)   // 152096 B
__global__ void __launch_bounds__(512, 1)
attn_k(const float* __restrict__ qg)
{
    extern __shared__ float smf[];
    float* s_kv  = smf;                // [49][512]  k: cols 0..255, v: 256..511
    float* s_out = smf + 49*512;       // [49][264]

    const int tid = threadIdx.x;
    const int b   = blockIdx.x;

    {   // stage KV
        const float4* src = (const float4*)(g_KV + (size_t)b * NTOK * 512);
        float4* dst = (float4*)s_kv;
        for (int u = tid; u < NTOK*128; u += 512) dst[u] = __ldg(src + u);
    }
    __syncthreads();

    const int w = tid >> 5, lane = tid & 31;
    const int h = w & 7, p = w >> 3;
    const int qi = p*32 + lane;
    const bool act = qi < NTOK;
    const int qis = act ? qi : 0;

    float qv[32];
    {
        const float4* qr = (const float4*)(qg + (((size_t)(b >> 6)*HEADS + h)*NTOK + qis)*HDIM);
        float m = act ? SCALE : 0.f;
        #pragma unroll
        for (int d4 = 0; d4 < 8; d4++) {
            float4 t = __ldg(qr + d4);
            qv[d4*4+0] = t.x*m; qv[d4*4+1] = t.y*m;
            qv[d4*4+2] = t.z*m; qv[d4*4+3] = t.w*m;
        }
    }

    float s[NTOK];
    float mx = -1e30f;
    #pragma unroll
    for (int kj = 0; kj < NTOK; kj++) {
        const float4* kr = (const float4*)(s_kv + kj*512 + h*HDIM);  // warp broadcast
        float sum = __ldg(g_biasT + (h*NTOK + kj)*NTOK + qis);
        #pragma unroll
        for (int d4 = 0; d4 < 8; d4++) {
            float4 kv4 = kr[d4];
            sum = fmaf(qv[d4*4+0], kv4.x, sum);
            sum = fmaf(qv[d4*4+1], kv4.y, sum);
            sum = fmaf(qv[d4*4+2], kv4.z, sum);
            sum = fmaf(qv[d4*4+3], kv4.w, sum);
        }
        s[kj] = sum;
        mx = fmaxf(mx, sum);
    }
    float den = 0.f;
    #pragma unroll
    for (int kj = 0; kj < NTOK; kj++) { s[kj] = __expf(s[kj] - mx); den += s[kj]; }
    float rinv = 1.f / den;

    float o[32];
    #pragma unroll
    for (int d = 0; d < 32; d++) o[d] = 0.f;
    #pragma unroll
    for (int kj = 0; kj < NTOK; kj++) {
        float pv = s[kj];
        const float4* vr = (const float4*)(s_kv + kj*512 + 256 + h*HDIM);
        #pragma unroll
        for (int d4 = 0; d4 < 8; d4++) {
            float4 vv = vr[d4];
            o[d4*4+0] = fmaf(pv, vv.x, o[d4*4+0]);
            o[d4*4+1] = fmaf(pv, vv.y, o[d4*4+1]);
            o[d4*4+2] = fmaf(pv, vv.z, o[d4*4+2]);
            o[d4*4+3] = fmaf(pv, vv.w, o[d4*4+3]);
        }
    }
    if (act) {
        float4* dst = (float4*)(s_out + qi*264 + h*HDIM);
        #pragma unroll
        for (int d4 = 0; d4 < 8; d4++)
            dst[d4] = make_float4(o[d4*4+0]*rinv, o[d4*4+1]*rinv,
                                  o[d4*4+2]*rinv, o[d4*4+3]*rinv);
    }
    __syncthreads();

    // convert to hi|lo|hi bf16 and store to g_A2
    __nv_bfloat16* dst = g_A2 + (size_t)b * NTOK * KD;
    for (int u = tid; u < NTOK*CDIM; u += 512) {
        int r = u >> 8, c = u & 255;
        float v = s_out[r*264 + c];
        __nv_bfloat16 hi = __float2bfloat16(v);
        __nv_bfloat16 lo = __float2bfloat16(v - __bfloat162float(hi));
        size_t rb = (size_t)r * KD;
        dst[rb + c]       = hi;
        dst[rb + 256 + c] = lo;
        dst[rb + 512 + c] = hi;
    }
}

// ---------------- launch ----------------
extern "C" void kernel_launch(void* const* d_in, const int* in_sizes, int n_in,
                              void* d_out, int out_size)
{
    const float* x      = (const float*)d_in[0];
    const float* qg     = (const float*)d_in[1];
    const float* qkv_w  = (const float*)d_in[2];
    const float* qkv_b  = (const float*)d_in[3];
    const float* proj_w = (const float*)d_in[4];
    const float* proj_b = (const float*)d_in[5];
    const float* rbt    = (const float*)d_in[6];
    float* out = (float*)d_out;
    (void)in_sizes; (void)n_in; (void)out_size;

    cudaFuncSetAttribute(gemm_k<512>, cudaFuncAttributeMaxDynamicSharedMemorySize, GSMEM);
    cudaFuncSetAttribute(gemm_k<256>, cudaFuncAttributeMaxDynamicSharedMemorySize, GSMEM);
    cudaFuncSetAttribute(attn_k,      cudaFuncAttributeMaxDynamicSharedMemorySize, ATTN_SMEM);

    prep_w<<<1536, 256>>>(qkv_w, proj_w, rbt);
    conv_x<<<TOKS, 256>>>(x);
    {
        dim3 g1(TOKS/128, 4);
        gemm_k<512><<<g1, 256, GSMEM>>>(qkv_b, nullptr);
    }
    attn_k<<<BWIN, 512, ATTN_SMEM>>>(qg);
    {
        dim3 g2(TOKS/128, 2);
        gemm_k<256><<<g2, 256, GSMEM>>>(proj_b, out);
    }
}